// round 6
// baseline (speedup 1.0000x reference)
#include <cuda_runtime.h>
#include <math.h>
#include <stdint.h>

// ---------------- problem constants ----------------
#define BN_  8192   // batch (GEMM M)
#define TN_  658    // seq len / final out features
#define TP_  672    // K-pad for layer1 (21 * 32)
#define IN_  7
#define D1_  1024
#define D2_  512
#define D3_  128
#define N4P_ 768    // w4 N padded (658 -> 768)

// ---------------- scratch ----------------
__device__ float g_xwT[(size_t)TN_ * BN_];   // [t][b] input projection
__device__ float g_hs [(size_t)BN_ * TP_];   // [b][t] row-major, tf32, K-padded
__device__ float g_c1 [(size_t)BN_ * D1_];
__device__ float g_c2 [(size_t)BN_ * D2_];
__device__ float g_c3 [(size_t)BN_ * D3_];
__device__ float g_w1c[D1_ * TP_];
__device__ float g_w2c[D2_ * D1_];
__device__ float g_w3c[D3_ * D2_];
__device__ float g_w4c[N4P_ * D3_];

// ---------------- helpers ----------------
__device__ __forceinline__ uint32_t smem_u32(const void* p) {
    uint32_t a;
    asm("{ .reg .u64 t; cvta.to.shared.u64 t, %1; cvt.u32.u64 %0, t; }" : "=r"(a) : "l"(p));
    return a;
}
__device__ __forceinline__ float cvt_tf32f(float x) {
    uint32_t u; asm("cvt.rna.tf32.f32 %0, %1;" : "=r"(u) : "f"(x));
    return __uint_as_float(u);
}
#define CP16(sa, ga) asm volatile("cp.async.cg.shared.global [%0], [%1], 16;" :: "r"(sa), "l"(ga))
#define CP_COMMIT()  asm volatile("cp.async.commit_group;" ::: "memory")
#define CP_WAIT0()   asm volatile("cp.async.wait_group 0;" ::: "memory")
#define CP_WAIT1()   asm volatile("cp.async.wait_group 1;" ::: "memory")

#define LDSM4(r0, r1, r2, r3, a)                                                 \
    asm volatile("ldmatrix.sync.aligned.m8n8.x4.shared.b16 {%0,%1,%2,%3}, [%4];" \
        : "=r"(r0), "=r"(r1), "=r"(r2), "=r"(r3) : "r"(a))

__device__ __forceinline__ void mma_tf32(float* d, const uint32_t* a, const uint32_t* b) {
    asm volatile(
        "mma.sync.aligned.m16n8k8.row.col.f32.tf32.tf32.f32 "
        "{%0,%1,%2,%3}, {%4,%5,%6,%7}, {%8,%9}, {%0,%1,%2,%3};"
        : "+f"(d[0]), "+f"(d[1]), "+f"(d[2]), "+f"(d[3])
        : "r"(a[0]), "r"(a[1]), "r"(a[2]), "r"(a[3]), "r"(b[0]), "r"(b[1]));
}

// ---------------- fused weight prep (pad + tf32 round) ----------------
#define WSEG1 (D1_ * TP_)
#define WSEG2 (D2_ * D1_)
#define WSEG3 (D3_ * D2_)
#define WSEG4 (N4P_ * D3_)
#define WTOT  (WSEG1 + WSEG2 + WSEG3 + WSEG4)

__global__ void wprep_all(const float* __restrict__ w1, const float* __restrict__ w2,
                          const float* __restrict__ w3, const float* __restrict__ w4,
                          float* __restrict__ w1c, float* __restrict__ w2c,
                          float* __restrict__ w3c, float* __restrict__ w4c)
{
    int idx = blockIdx.x * blockDim.x + threadIdx.x;
    if (idx < WSEG1) {
        int n = idx / TP_, k = idx - n * TP_;
        w1c[idx] = (k < TN_) ? cvt_tf32f(w1[n * TN_ + k]) : 0.0f;
        return;
    }
    idx -= WSEG1;
    if (idx < WSEG2) { w2c[idx] = cvt_tf32f(w2[idx]); return; }
    idx -= WSEG2;
    if (idx < WSEG3) { w3c[idx] = cvt_tf32f(w3[idx]); return; }
    idx -= WSEG3;
    if (idx < WSEG4) {
        int n = idx / D3_, k = idx - n * D3_;
        w4c[idx] = (n < TN_) ? cvt_tf32f(w4[n * D3_ + k]) : 0.0f;
    }
}

// ---------------- input projection: xwT[t][b] ----------------
// block = 256 threads handles 32 b's; t-tiles of 32. x staged via coalesced
// float2 loads; compute reads smem (7*lane mod 32 -> conflict-free).
__global__ __launch_bounds__(256)
void xw_kernel(const float* __restrict__ x,
               const float* __restrict__ Wih,
               const float* __restrict__ bih,
               const float* __restrict__ bhh,
               float* __restrict__ xwT)
{
    __shared__ float raw[32 * 224];
    __shared__ float tr[32 * 33];
    int tid = threadIdx.x;
    int lane = tid & 31, w = tid >> 5;
    int b0 = blockIdx.x * 32;

    float w0 = Wih[0], w1 = Wih[1], w2 = Wih[2], w3 = Wih[3];
    float w4 = Wih[4], w5 = Wih[5], w6 = Wih[6];
    float bias = bih[0] + bhh[0];

    for (int t0 = 0; t0 < TN_; t0 += 32) {
        int nt = (TN_ - t0 < 32) ? (TN_ - t0) : 32;
        int nf2 = nt * 7 / 2;                 // float2 per row (nt*7 always even here)
        int tot = 32 * nf2;
        for (int l = tid; l < tot; l += 256) {
            int r = l / nf2, o = l - r * nf2;
            const float2 v = *(const float2*)(x + (size_t)(b0 + r) * (TN_ * IN_) + t0 * IN_ + 2 * o);
            raw[r * 224 + 2 * o]     = v.x;
            raw[r * 224 + 2 * o + 1] = v.y;
        }
        __syncthreads();

        #pragma unroll
        for (int rr = 0; rr < 4; rr++) {
            int r = w + rr * 8;
            float v = 0.0f;
            if (lane < nt) {
                const float* p = raw + r * 224 + lane * 7;
                v = bias;
                v = fmaf(p[0], w0, v);
                v = fmaf(p[1], w1, v);
                v = fmaf(p[2], w2, v);
                v = fmaf(p[3], w3, v);
                v = fmaf(p[4], w4, v);
                v = fmaf(p[5], w5, v);
                v = fmaf(p[6], w6, v);
            }
            tr[lane * 33 + r] = v;
        }
        __syncthreads();
        #pragma unroll
        for (int i = 0; i < 4; i++) {
            int tt = w * 4 + i;
            int t = t0 + tt;
            if (t < TN_) xwT[(size_t)t * BN_ + b0 + lane] = tr[tt * 33 + lane];
        }
        __syncthreads();
    }
}

// ---------------- RNN: recurrence + in-block transpose -> hs[b][t] ----------------
__global__ __launch_bounds__(128)
void rnn_kernel(const float* __restrict__ xwT,
                const float* __restrict__ h0,
                const float* __restrict__ Whh,
                float* __restrict__ hs,
                float* __restrict__ hidden)
{
    __shared__ float buf[128 * 33];
    int tid = threadIdx.x;
    int lane = tid & 31, w = tid >> 5;
    int bBase = blockIdx.x * 128;
    int b = bBase + tid;

    float a = Whh[0];
    float h = h0[b];
    float nx = xwT[b];

    for (int t0 = 0; t0 < TP_; t0 += 32) {
        #pragma unroll 4
        for (int j = 0; j < 32; j++) {
            int t = t0 + j;
            float v = 0.0f;
            if (t < TN_) {
                float cur = nx;
                if (t + 1 < TN_) nx = xwT[(size_t)(t + 1) * BN_ + b];
                h = tanhf(fmaf(a, h, cur));
                v = cvt_tf32f(h);
            }
            buf[tid * 33 + j] = v;
        }
        __syncthreads();
        #pragma unroll 4
        for (int rr = 0; rr < 32; rr++) {
            int row = w * 32 + rr;
            hs[(size_t)(bBase + row) * TP_ + t0 + lane] = buf[row * 33 + lane];
        }
        __syncthreads();
    }
    if (hidden) hidden[b] = h;
}

// ---------------- mma.sync tf32 GEMM with ldmatrix fragments ----------------
// C[m,n] = sum_k A[m,k]*B[n,k] + bias[n]. BM = MT*32, BN = 128, BK = 32.
// 256 threads = 8 warps (2 m x 4 n), warp tile (MT*16) x 32. smem rows: 36 floats.
template<int MT, bool RELU, bool GUARDN, bool CVTOUT>
__global__ __launch_bounds__(256, 2)
void gemm_mma(const float* __restrict__ A, int lda,
              const float* __restrict__ Bw, int ldb,
              const float* __restrict__ bias,
              float* __restrict__ C, int ldc, int Nreal, int K)
{
    constexpr int BM = MT * 32;
    constexpr int A_STAGE = BM * 36;     // floats
    constexpr int B_STAGE = 128 * 36;

    extern __shared__ float sm[];
    float* As = sm;
    float* Bs = sm + 2 * A_STAGE;

    int tid = threadIdx.x;
    int lane = tid & 31;
    int wid  = tid >> 5;
    int wm = wid & 1;
    int wn = wid >> 1;
    int grp = lane >> 2;
    int qk  = lane & 3;
    int m0 = blockIdx.y * BM;
    int n0 = blockIdx.x * 128;

    // ldmatrix per-lane base addresses (bytes)
    int aRow = wm * (MT * 16) + ((lane >> 3) & 1) * 8 + (lane & 7);
    int aCol = ((lane >> 4) & 1) * 4;
    uint32_t aBase = smem_u32(As) + (uint32_t)(aRow * 36 + aCol) * 4;
    int bRow = wn * 32 + ((lane >> 4) & 1) * 8 + (lane & 7);
    int bCol = ((lane >> 3) & 1) * 4;
    uint32_t bBase = smem_u32(Bs) + (uint32_t)(bRow * 36 + bCol) * 4;

    float acc[MT][4][4];
    #pragma unroll
    for (int i = 0; i < MT; i++)
        #pragma unroll
        for (int j = 0; j < 4; j++)
            #pragma unroll
            for (int q = 0; q < 4; q++) acc[i][j][q] = 0.0f;

    const int KT = K >> 5;

    auto load_stage = [&](int kt, int s) {
        float* aS = As + s * A_STAGE;
        float* bS = Bs + s * B_STAGE;
        const float* Ap = A + (size_t)m0 * lda + kt * 32;
        #pragma unroll
        for (int i = 0; i < BM / 32; i++) {
            int c = i * 256 + tid;
            int r = c >> 3, co = (c & 7) << 2;
            CP16(smem_u32(aS + r * 36 + co), Ap + (size_t)r * lda + co);
        }
        const float* Bp = Bw + (size_t)n0 * ldb + kt * 32;
        #pragma unroll
        for (int i = 0; i < 4; i++) {
            int c = i * 256 + tid;
            int r = c >> 3, co = (c & 7) << 2;
            CP16(smem_u32(bS + r * 36 + co), Bp + (size_t)r * ldb + co);
        }
        CP_COMMIT();
    };

    load_stage(0, 0);

    for (int kt = 0; kt < KT; kt++) {
        int s = kt & 1;
        if (kt + 1 < KT) { load_stage(kt + 1, s ^ 1); CP_WAIT1(); }
        else             { CP_WAIT0(); }
        __syncthreads();

        uint32_t aSt = aBase + (uint32_t)(s * A_STAGE) * 4;
        uint32_t bSt = bBase + (uint32_t)(s * B_STAGE) * 4;

        #pragma unroll
        for (int ks = 0; ks < 4; ks++) {
            uint32_t af[MT][4], bf[4][2];
            uint32_t aAddr = aSt + ks * 32;
            #pragma unroll
            for (int mt = 0; mt < MT; mt++)
                LDSM4(af[mt][0], af[mt][1], af[mt][2], af[mt][3],
                      aAddr + (uint32_t)(mt * 16 * 36) * 4);
            uint32_t bAddr = bSt + ks * 32;
            #pragma unroll
            for (int ntp = 0; ntp < 2; ntp++)
                LDSM4(bf[2 * ntp][0], bf[2 * ntp][1], bf[2 * ntp + 1][0], bf[2 * ntp + 1][1],
                      bAddr + (uint32_t)(ntp * 16 * 36) * 4);
            #pragma unroll
            for (int mt = 0; mt < MT; mt++)
                #pragma unroll
                for (int nt = 0; nt < 4; nt++)
                    mma_tf32(acc[mt][nt], af[mt], bf[nt]);
        }
        __syncthreads();
    }

    // ---- epilogue ----
    #pragma unroll
    for (int mt = 0; mt < MT; mt++) {
        int r0 = m0 + wm * (MT * 16) + mt * 16 + grp;
        #pragma unroll
        for (int nt = 0; nt < 4; nt++) {
            int nc = n0 + wn * 32 + nt * 8 + 2 * qk;
            if (GUARDN && nc >= Nreal) continue;
            float b0v = bias[nc], b1v = bias[nc + 1];
            float v00 = acc[mt][nt][0] + b0v, v01 = acc[mt][nt][1] + b1v;
            float v10 = acc[mt][nt][2] + b0v, v11 = acc[mt][nt][3] + b1v;
            if (RELU) {
                v00 = fmaxf(v00, 0.0f); v01 = fmaxf(v01, 0.0f);
                v10 = fmaxf(v10, 0.0f); v11 = fmaxf(v11, 0.0f);
            }
            if (CVTOUT) {
                v00 = cvt_tf32f(v00); v01 = cvt_tf32f(v01);
                v10 = cvt_tf32f(v10); v11 = cvt_tf32f(v11);
            }
            *(float2*)(C + (size_t)r0 * ldc + nc)       = make_float2(v00, v01);
            *(float2*)(C + (size_t)(r0 + 8) * ldc + nc) = make_float2(v10, v11);
        }
    }
}

// ---------------- launcher ----------------
#define SMEM_MT4 (2 * (128 * 36 + 128 * 36) * 4)
#define SMEM_MT2 (2 * (64 * 36 + 128 * 36) * 4)

extern "C" void kernel_launch(void* const* d_in, const int* in_sizes, int n_in,
                              void* d_out, int out_size)
{
    const float* x   = (const float*)d_in[0];
    const float* h0  = (const float*)d_in[1];
    const float* Wih = (const float*)d_in[2];
    const float* Whh = (const float*)d_in[3];
    const float* bih = (const float*)d_in[4];
    const float* bhh = (const float*)d_in[5];
    const float* w1  = (const float*)d_in[6];
    const float* b1  = (const float*)d_in[7];
    const float* w2  = (const float*)d_in[8];
    const float* b2  = (const float*)d_in[9];
    const float* w3  = (const float*)d_in[10];
    const float* b3  = (const float*)d_in[11];
    const float* w4  = (const float*)d_in[12];
    const float* b4  = (const float*)d_in[13];
    float* out = (float*)d_out;

    float *xwT, *hs, *c1, *c2, *c3, *w1c, *w2c, *w3c, *w4c;
    cudaGetSymbolAddress((void**)&xwT, g_xwT);
    cudaGetSymbolAddress((void**)&hs,  g_hs);
    cudaGetSymbolAddress((void**)&c1,  g_c1);
    cudaGetSymbolAddress((void**)&c2,  g_c2);
    cudaGetSymbolAddress((void**)&c3,  g_c3);
    cudaGetSymbolAddress((void**)&w1c, g_w1c);
    cudaGetSymbolAddress((void**)&w2c, g_w2c);
    cudaGetSymbolAddress((void**)&w3c, g_w3c);
    cudaGetSymbolAddress((void**)&w4c, g_w4c);

    cudaFuncSetAttribute(gemm_mma<4, true,  false, true >, cudaFuncAttributeMaxDynamicSharedMemorySize, SMEM_MT4);
    cudaFuncSetAttribute(gemm_mma<2, true,  false, true >, cudaFuncAttributeMaxDynamicSharedMemorySize, SMEM_MT2);
    cudaFuncSetAttribute(gemm_mma<4, false, true,  false>, cudaFuncAttributeMaxDynamicSharedMemorySize, SMEM_MT4);

    // weight prep (single fused launch)
    wprep_all<<<(WTOT + 255) / 256, 256>>>(w1, w2, w3, w4, w1c, w2c, w3c, w4c);

    // input projection, then recurrence with fused transpose (hs row-major)
    xw_kernel<<<BN_ / 32, 256>>>(x, Wih, bih, bhh, xwT);
    float* hidden = (out_size >= BN_ * TN_ + BN_) ? (out + (size_t)BN_ * TN_) : nullptr;
    rnn_kernel<<<BN_ / 128, 128>>>(xwT, h0, Whh, hs, hidden);

    // GEMM chain on mma.sync tf32 (all row-major, ldmatrix fragments)
    gemm_mma<4, true,  false, true ><<<dim3(D1_ / 128, BN_ / 128), 256, SMEM_MT4>>>(hs, TP_,  w1c, TP_,  b1, c1,  D1_, D1_, TP_);
    gemm_mma<4, true,  false, true ><<<dim3(D2_ / 128, BN_ / 128), 256, SMEM_MT4>>>(c1, D1_,  w2c, D1_,  b2, c2,  D2_, D2_, D1_);
    gemm_mma<2, true,  false, true ><<<dim3(D3_ / 128, BN_ / 64 ), 256, SMEM_MT2>>>(c2, D2_,  w3c, D2_,  b3, c3,  D3_, D3_, D2_);
    gemm_mma<4, false, true,  false><<<dim3(N4P_ / 128, BN_ / 128), 256, SMEM_MT4>>>(c3, D3_,  w4c, D3_,  b4, out, TN_, TN_, D3_);
}

// round 7
// speedup vs baseline: 1.8792x; 1.8792x over previous
#include <cuda_runtime.h>
#include <math.h>
#include <stdint.h>

// ---------------- problem constants ----------------
#define BN_  8192   // batch (GEMM M)
#define TN_  658    // seq len / final out features
#define TP_  672    // K-pad for layer1 (21 * 32)
#define IN_  7
#define D1_  1024
#define D2_  512
#define D3_  128
#define N4P_ 768    // w4 N padded (658 -> 768)

// ---------------- scratch ----------------
__device__ float g_xwT[(size_t)TN_ * BN_];   // [t][b] input projection
__device__ float g_hsT[(size_t)TP_ * BN_];   // [t][b] tf32, K-padded (A^T of GEMM1)
__device__ float g_c1 [(size_t)BN_ * D1_];
__device__ float g_c2 [(size_t)BN_ * D2_];
__device__ float g_c3 [(size_t)BN_ * D3_];
__device__ float g_w1c[D1_ * TP_];
__device__ float g_w2c[D2_ * D1_];
__device__ float g_w3c[D3_ * D2_];
__device__ float g_w4c[N4P_ * D3_];

// ---------------- helpers ----------------
__device__ __forceinline__ uint32_t smem_u32(const void* p) {
    uint32_t a;
    asm("{ .reg .u64 t; cvta.to.shared.u64 t, %1; cvt.u32.u64 %0, t; }" : "=r"(a) : "l"(p));
    return a;
}
__device__ __forceinline__ float cvt_tf32f(float x) {
    uint32_t u; asm("cvt.rna.tf32.f32 %0, %1;" : "=r"(u) : "f"(x));
    return __uint_as_float(u);
}
#define CP16(sa, ga) asm volatile("cp.async.cg.shared.global [%0], [%1], 16;" :: "r"(sa), "l"(ga))
#define CP_COMMIT()  asm volatile("cp.async.commit_group;" ::: "memory")
#define CP_WAIT0()   asm volatile("cp.async.wait_group 0;" ::: "memory")
#define CP_WAIT1()   asm volatile("cp.async.wait_group 1;" ::: "memory")
#define CP_WAIT2()   asm volatile("cp.async.wait_group 2;" ::: "memory")

#define LDSM4(r0, r1, r2, r3, a)                                                 \
    asm volatile("ldmatrix.sync.aligned.m8n8.x4.shared.b16 {%0,%1,%2,%3}, [%4];" \
        : "=r"(r0), "=r"(r1), "=r"(r2), "=r"(r3) : "r"(a))

__device__ __forceinline__ void mma_tf32(float* d, const uint32_t* a, const uint32_t* b) {
    asm volatile(
        "mma.sync.aligned.m16n8k8.row.col.f32.tf32.tf32.f32 "
        "{%0,%1,%2,%3}, {%4,%5,%6,%7}, {%8,%9}, {%0,%1,%2,%3};"
        : "+f"(d[0]), "+f"(d[1]), "+f"(d[2]), "+f"(d[3])
        : "r"(a[0]), "r"(a[1]), "r"(a[2]), "r"(a[3]), "r"(b[0]), "r"(b[1]));
}

// ---------------- fused weight prep (pad + tf32 round) ----------------
#define WSEG1 (D1_ * TP_)
#define WSEG2 (D2_ * D1_)
#define WSEG3 (D3_ * D2_)
#define WSEG4 (N4P_ * D3_)
#define WTOT  (WSEG1 + WSEG2 + WSEG3 + WSEG4)

__global__ void wprep_all(const float* __restrict__ w1, const float* __restrict__ w2,
                          const float* __restrict__ w3, const float* __restrict__ w4,
                          float* __restrict__ w1c, float* __restrict__ w2c,
                          float* __restrict__ w3c, float* __restrict__ w4c)
{
    int idx = blockIdx.x * blockDim.x + threadIdx.x;
    if (idx < WSEG1) {
        int n = idx / TP_, k = idx - n * TP_;
        w1c[idx] = (k < TN_) ? cvt_tf32f(w1[n * TN_ + k]) : 0.0f;
        return;
    }
    idx -= WSEG1;
    if (idx < WSEG2) { w2c[idx] = cvt_tf32f(w2[idx]); return; }
    idx -= WSEG2;
    if (idx < WSEG3) { w3c[idx] = cvt_tf32f(w3[idx]); return; }
    idx -= WSEG3;
    if (idx < WSEG4) {
        int n = idx / D3_, k = idx - n * D3_;
        w4c[idx] = (n < TN_) ? cvt_tf32f(w4[n * D3_ + k]) : 0.0f;
    }
}

// ---------------- input projection (round-5 version, known good) ----------------
__global__ __launch_bounds__(256)
void xw_kernel(const float* __restrict__ x,
               const float* __restrict__ Wih,
               const float* __restrict__ bih,
               const float* __restrict__ bhh,
               float* __restrict__ xwT)
{
    __shared__ float sm[32 * 33];
    int tid = threadIdx.x;
    int lane = tid & 31, w = tid >> 5;
    int b0 = blockIdx.x * 32;

    float w0 = Wih[0], w1 = Wih[1], w2 = Wih[2], w3 = Wih[3];
    float w4 = Wih[4], w5 = Wih[5], w6 = Wih[6];
    float bias = bih[0] + bhh[0];

    for (int t0 = 0; t0 < TN_; t0 += 32) {
        #pragma unroll
        for (int rr = 0; rr < 4; rr++) {
            int r = w + rr * 8;
            int t = t0 + lane;
            float v = 0.0f;
            if (t < TN_) {
                const float* p = x + ((size_t)(b0 + r) * TN_ + t) * IN_;
                v = bias;
                v = fmaf(p[0], w0, v);
                v = fmaf(p[1], w1, v);
                v = fmaf(p[2], w2, v);
                v = fmaf(p[3], w3, v);
                v = fmaf(p[4], w4, v);
                v = fmaf(p[5], w5, v);
                v = fmaf(p[6], w6, v);
            }
            sm[lane * 33 + r] = v;
        }
        __syncthreads();
        #pragma unroll
        for (int i = 0; i < 4; i++) {
            int tt = w * 4 + i;
            int t = t0 + tt;
            if (t < TN_) xwT[(size_t)t * BN_ + b0 + lane] = sm[tt * 33 + lane];
        }
        __syncthreads();
    }
}

// ---------------- RNN: recurrence with cp.async smem ring ----------------
// 128 threads / block, 64 blocks. Ring of 4 stages x (32 t x 128 b) floats.
#define RNN_TILES  (TP_ / 32)          // 21
#define RNN_STAGE  (32 * 128)          // floats per stage
#define RNN_SMEM   (4 * RNN_STAGE * 4) // 64 KB

__global__ __launch_bounds__(128)
void rnn_kernel(const float* __restrict__ xwT,
                const float* __restrict__ h0,
                const float* __restrict__ Whh,
                float* __restrict__ hsT,
                float* __restrict__ hidden)
{
    extern __shared__ float ring[];
    int tid = threadIdx.x;
    int b0 = blockIdx.x * 128;
    int b = b0 + tid;

    float a = Whh[0];
    float h = h0[b];

    auto load_tile = [&](int tt) {
        int t0 = tt * 32;
        float* dst = ring + (tt & 3) * RNN_STAGE;
        #pragma unroll
        for (int i = 0; i < 8; i++) {
            int c = i * 128 + tid;
            int r = c >> 5, co = (c & 31) << 2;
            int t = t0 + r;
            if (t < TN_)
                CP16(smem_u32(dst + r * 128 + co), xwT + (size_t)t * BN_ + b0 + co);
        }
        CP_COMMIT();
    };

    load_tile(0); load_tile(1); load_tile(2);

    for (int tt = 0; tt < RNN_TILES; tt++) {
        if (tt + 3 < RNN_TILES) load_tile(tt + 3);
        else                    CP_COMMIT();     // keep group count uniform
        CP_WAIT2();
        __syncthreads();

        int t0 = tt * 32;
        const float* col = ring + (tt & 3) * RNN_STAGE + tid;
        int jmax = (TN_ - t0 < 32) ? (TN_ - t0) : 32;
        float nxt = col[0];
        #pragma unroll 4
        for (int j = 0; j < jmax; j++) {
            float cur = nxt;
            if (j + 1 < jmax) nxt = col[(j + 1) * 128];
            h = tanhf(fmaf(a, h, cur));
            hsT[(size_t)(t0 + j) * BN_ + b] = cvt_tf32f(h);
        }
        __syncthreads();
    }

    #pragma unroll
    for (int t = TN_; t < TP_; t++) hsT[(size_t)t * BN_ + b] = 0.0f;
    if (hidden) hidden[b] = h;
}

// ---------------- mma.sync tf32 GEMM ----------------
// C[m,n] = sum_k A[m,k]*B[n,k] + bias[n]. BM = MT*32, BN = 128, BK = 32.
// 256 threads = 8 warps (2 m x 4 n). B fragments via ldmatrix.
// ATRANS: A given as AT[k][M]; smem As [32][136], scalar A fragments.
// else:   A row-major; smem As [BM][36], A fragments via ldmatrix.
template<int MT, bool ATRANS, bool RELU, bool GUARDN, bool CVTOUT>
__global__ __launch_bounds__(256, 2)
void gemm_mma(const float* __restrict__ A, int lda,
              const float* __restrict__ Bw, int ldb,
              const float* __restrict__ bias,
              float* __restrict__ C, int ldc, int Nreal, int K)
{
    constexpr int BM = MT * 32;
    constexpr int A_STAGE = ATRANS ? 32 * 136 : BM * 36;
    constexpr int B_STAGE = 128 * 36;

    extern __shared__ float sm[];
    float* As = sm;
    float* Bs = sm + 2 * A_STAGE;

    int tid = threadIdx.x;
    int lane = tid & 31;
    int wid  = tid >> 5;
    int wm = wid & 1;
    int wn = wid >> 1;
    int grp = lane >> 2;
    int qk  = lane & 3;
    int m0 = blockIdx.y * BM;
    int n0 = blockIdx.x * 128;

    // ldmatrix per-lane base addresses
    int aRow = wm * (MT * 16) + ((lane >> 3) & 1) * 8 + (lane & 7);
    int aCol = ((lane >> 4) & 1) * 4;
    uint32_t aBase = smem_u32(As) + (uint32_t)(aRow * 36 + aCol) * 4;
    int bRow = wn * 32 + ((lane >> 4) & 1) * 8 + (lane & 7);
    int bCol = ((lane >> 3) & 1) * 4;
    uint32_t bBase = smem_u32(Bs) + (uint32_t)(bRow * 36 + bCol) * 4;

    float acc[MT][4][4];
    #pragma unroll
    for (int i = 0; i < MT; i++)
        #pragma unroll
        for (int j = 0; j < 4; j++)
            #pragma unroll
            for (int q = 0; q < 4; q++) acc[i][j][q] = 0.0f;

    const int KT = K >> 5;

    auto load_stage = [&](int kt, int s) {
        float* aS = As + s * A_STAGE;
        float* bS = Bs + s * B_STAGE;
        if (ATRANS) {
            const float* Ap = A + (size_t)(kt * 32) * lda + m0;
            #pragma unroll
            for (int i = 0; i < 4; i++) {
                int c = i * 256 + tid;
                int r = c >> 5, co = (c & 31) << 2;
                CP16(smem_u32(aS + r * 136 + co), Ap + (size_t)r * lda + co);
            }
        } else {
            const float* Ap = A + (size_t)m0 * lda + kt * 32;
            #pragma unroll
            for (int i = 0; i < BM / 32; i++) {
                int c = i * 256 + tid;
                int r = c >> 3, co = (c & 7) << 2;
                CP16(smem_u32(aS + r * 36 + co), Ap + (size_t)r * lda + co);
            }
        }
        const float* Bp = Bw + (size_t)n0 * ldb + kt * 32;
        #pragma unroll
        for (int i = 0; i < 4; i++) {
            int c = i * 256 + tid;
            int r = c >> 3, co = (c & 7) << 2;
            CP16(smem_u32(bS + r * 36 + co), Bp + (size_t)r * ldb + co);
        }
        CP_COMMIT();
    };

    load_stage(0, 0);

    for (int kt = 0; kt < KT; kt++) {
        int s = kt & 1;
        if (kt + 1 < KT) { load_stage(kt + 1, s ^ 1); CP_WAIT1(); }
        else             { CP_WAIT0(); }
        __syncthreads();

        const float* aB = As + s * A_STAGE;
        uint32_t aSt = aBase + (uint32_t)(s * A_STAGE) * 4;
        uint32_t bSt = bBase + (uint32_t)(s * B_STAGE) * 4;

        #pragma unroll
        for (int ks = 0; ks < 4; ks++) {
            int kb = ks * 8 + qk;
            uint32_t af[MT][4], bf[4][2];
            if (ATRANS) {
                #pragma unroll
                for (int mt = 0; mt < MT; mt++) {
                    int mrow = wm * (MT * 16) + mt * 16 + grp;
                    af[mt][0] = __float_as_uint(aB[kb * 136 + mrow]);
                    af[mt][1] = __float_as_uint(aB[kb * 136 + mrow + 8]);
                    af[mt][2] = __float_as_uint(aB[(kb + 4) * 136 + mrow]);
                    af[mt][3] = __float_as_uint(aB[(kb + 4) * 136 + mrow + 8]);
                }
            } else {
                uint32_t aAddr = aSt + ks * 32;
                #pragma unroll
                for (int mt = 0; mt < MT; mt++)
                    LDSM4(af[mt][0], af[mt][1], af[mt][2], af[mt][3],
                          aAddr + (uint32_t)(mt * 16 * 36) * 4);
            }
            uint32_t bAddr = bSt + ks * 32;
            #pragma unroll
            for (int ntp = 0; ntp < 2; ntp++)
                LDSM4(bf[2 * ntp][0], bf[2 * ntp][1], bf[2 * ntp + 1][0], bf[2 * ntp + 1][1],
                      bAddr + (uint32_t)(ntp * 16 * 36) * 4);
            #pragma unroll
            for (int mt = 0; mt < MT; mt++)
                #pragma unroll
                for (int nt = 0; nt < 4; nt++)
                    mma_tf32(acc[mt][nt], af[mt], bf[nt]);
        }
        __syncthreads();
    }

    // ---- epilogue ----
    #pragma unroll
    for (int mt = 0; mt < MT; mt++) {
        int r0 = m0 + wm * (MT * 16) + mt * 16 + grp;
        #pragma unroll
        for (int nt = 0; nt < 4; nt++) {
            int nc = n0 + wn * 32 + nt * 8 + 2 * qk;
            if (GUARDN && nc >= Nreal) continue;
            float b0v = bias[nc], b1v = bias[nc + 1];
            float v00 = acc[mt][nt][0] + b0v, v01 = acc[mt][nt][1] + b1v;
            float v10 = acc[mt][nt][2] + b0v, v11 = acc[mt][nt][3] + b1v;
            if (RELU) {
                v00 = fmaxf(v00, 0.0f); v01 = fmaxf(v01, 0.0f);
                v10 = fmaxf(v10, 0.0f); v11 = fmaxf(v11, 0.0f);
            }
            if (CVTOUT) {
                v00 = cvt_tf32f(v00); v01 = cvt_tf32f(v01);
                v10 = cvt_tf32f(v10); v11 = cvt_tf32f(v11);
            }
            *(float2*)(C + (size_t)r0 * ldc + nc)       = make_float2(v00, v01);
            *(float2*)(C + (size_t)(r0 + 8) * ldc + nc) = make_float2(v10, v11);
        }
    }
}

// ---------------- launcher ----------------
#define SMEM_G1  (2 * (32 * 136 + 128 * 36) * 4)
#define SMEM_MT4 (2 * (128 * 36 + 128 * 36) * 4)
#define SMEM_MT2 (2 * (64 * 36 + 128 * 36) * 4)

extern "C" void kernel_launch(void* const* d_in, const int* in_sizes, int n_in,
                              void* d_out, int out_size)
{
    const float* x   = (const float*)d_in[0];
    const float* h0  = (const float*)d_in[1];
    const float* Wih = (const float*)d_in[2];
    const float* Whh = (const float*)d_in[3];
    const float* bih = (const float*)d_in[4];
    const float* bhh = (const float*)d_in[5];
    const float* w1  = (const float*)d_in[6];
    const float* b1  = (const float*)d_in[7];
    const float* w2  = (const float*)d_in[8];
    const float* b2  = (const float*)d_in[9];
    const float* w3  = (const float*)d_in[10];
    const float* b3  = (const float*)d_in[11];
    const float* w4  = (const float*)d_in[12];
    const float* b4  = (const float*)d_in[13];
    float* out = (float*)d_out;

    float *xwT, *hsT, *c1, *c2, *c3, *w1c, *w2c, *w3c, *w4c;
    cudaGetSymbolAddress((void**)&xwT, g_xwT);
    cudaGetSymbolAddress((void**)&hsT, g_hsT);
    cudaGetSymbolAddress((void**)&c1,  g_c1);
    cudaGetSymbolAddress((void**)&c2,  g_c2);
    cudaGetSymbolAddress((void**)&c3,  g_c3);
    cudaGetSymbolAddress((void**)&w1c, g_w1c);
    cudaGetSymbolAddress((void**)&w2c, g_w2c);
    cudaGetSymbolAddress((void**)&w3c, g_w3c);
    cudaGetSymbolAddress((void**)&w4c, g_w4c);

    cudaFuncSetAttribute(rnn_kernel, cudaFuncAttributeMaxDynamicSharedMemorySize, RNN_SMEM);
    cudaFuncSetAttribute(gemm_mma<4, true,  true,  false, true >, cudaFuncAttributeMaxDynamicSharedMemorySize, SMEM_G1);
    cudaFuncSetAttribute(gemm_mma<4, false, true,  false, true >, cudaFuncAttributeMaxDynamicSharedMemorySize, SMEM_MT4);
    cudaFuncSetAttribute(gemm_mma<2, false, true,  false, true >, cudaFuncAttributeMaxDynamicSharedMemorySize, SMEM_MT2);
    cudaFuncSetAttribute(gemm_mma<4, false, false, true,  false>, cudaFuncAttributeMaxDynamicSharedMemorySize, SMEM_MT4);

    // weight prep (single fused launch)
    wprep_all<<<(WTOT + 255) / 256, 256>>>(w1, w2, w3, w4, w1c, w2c, w3c, w4c);

    // input projection, then recurrence with deep prefetch (hsT [t][b])
    xw_kernel<<<BN_ / 32, 256>>>(x, Wih, bih, bhh, xwT);
    float* hidden = (out_size >= BN_ * TN_ + BN_) ? (out + (size_t)BN_ * TN_) : nullptr;
    rnn_kernel<<<BN_ / 128, 128, RNN_SMEM>>>(xwT, h0, Whh, hsT, hidden);

    // GEMM chain on mma.sync tf32
    gemm_mma<4, true,  true,  false, true ><<<dim3(D1_ / 128, BN_ / 128), 256, SMEM_G1 >>>(hsT, BN_, w1c, TP_,  b1, c1,  D1_, D1_, TP_);
    gemm_mma<4, false, true,  false, true ><<<dim3(D2_ / 128, BN_ / 128), 256, SMEM_MT4>>>(c1,  D1_, w2c, D1_,  b2, c2,  D2_, D2_, D1_);
    gemm_mma<2, false, true,  false, true ><<<dim3(D3_ / 128, BN_ / 64 ), 256, SMEM_MT2>>>(c2,  D2_, w3c, D2_,  b3, c3,  D3_, D3_, D2_);
    gemm_mma<4, false, false, true,  false><<<dim3(N4P_ / 128, BN_ / 128), 256, SMEM_MT4>>>(c3,  D3_, w4c, D3_,  b4, out, TN_, TN_, D3_);
}

// round 8
// speedup vs baseline: 2.4818x; 1.3206x over previous
#include <cuda_runtime.h>
#include <cuda_fp16.h>
#include <math.h>
#include <stdint.h>

// ---------------- problem constants ----------------
#define BN_  8192   // batch (GEMM M)
#define TN_  658    // seq len / final out features
#define TP_  672    // K-pad for layer1 (21 * 32)
#define IN_  7
#define D1_  1024
#define D2_  512
#define D3_  128
#define N4P_ 768    // w4 N padded (658 -> 768)

// ---------------- scratch ----------------
__device__ float  g_xwT[(size_t)TN_ * BN_];   // [t][b] input projection (fp32)
__device__ __half g_hsT[(size_t)TP_ * BN_];   // [t][b] fp16, K-padded (A^T of GEMM1)
__device__ __half g_c1 [(size_t)BN_ * D1_];
__device__ __half g_c2 [(size_t)BN_ * D2_];
__device__ __half g_c3 [(size_t)BN_ * D3_];
__device__ __half g_w1c[D1_ * TP_];
__device__ __half g_w2c[D2_ * D1_];
__device__ __half g_w3c[D3_ * D2_];
__device__ __half g_w4c[N4P_ * D3_];

// ---------------- helpers ----------------
__device__ __forceinline__ uint32_t smem_u32(const void* p) {
    uint32_t a;
    asm("{ .reg .u64 t; cvta.to.shared.u64 t, %1; cvt.u32.u64 %0, t; }" : "=r"(a) : "l"(p));
    return a;
}
#define CP16(sa, ga) asm volatile("cp.async.cg.shared.global [%0], [%1], 16;" :: "r"(sa), "l"(ga))
#define CP_COMMIT()  asm volatile("cp.async.commit_group;" ::: "memory")
#define CP_WAIT2()   asm volatile("cp.async.wait_group 2;" ::: "memory")
#define CP_WAIT0()   asm volatile("cp.async.wait_group 0;" ::: "memory")

#define LDSM4(r0, r1, r2, r3, a)                                                 \
    asm volatile("ldmatrix.sync.aligned.m8n8.x4.shared.b16 {%0,%1,%2,%3}, [%4];" \
        : "=r"(r0), "=r"(r1), "=r"(r2), "=r"(r3) : "r"(a))
#define LDSM4T(r0, r1, r2, r3, a)                                                      \
    asm volatile("ldmatrix.sync.aligned.m8n8.x4.trans.shared.b16 {%0,%1,%2,%3}, [%4];" \
        : "=r"(r0), "=r"(r1), "=r"(r2), "=r"(r3) : "r"(a))

__device__ __forceinline__ void mma_f16(float* d, const uint32_t* a, const uint32_t* b) {
    asm volatile(
        "mma.sync.aligned.m16n8k16.row.col.f32.f16.f16.f32 "
        "{%0,%1,%2,%3}, {%4,%5,%6,%7}, {%8,%9}, {%0,%1,%2,%3};"
        : "+f"(d[0]), "+f"(d[1]), "+f"(d[2]), "+f"(d[3])
        : "r"(a[0]), "r"(a[1]), "r"(a[2]), "r"(a[3]), "r"(b[0]), "r"(b[1]));
}

// ---------------- fused weight prep (pad + fp16 convert) ----------------
#define WSEG1 (D1_ * TP_)
#define WSEG2 (D2_ * D1_)
#define WSEG3 (D3_ * D2_)
#define WSEG4 (N4P_ * D3_)
#define WTOT  (WSEG1 + WSEG2 + WSEG3 + WSEG4)

__global__ void wprep_all(const float* __restrict__ w1, const float* __restrict__ w2,
                          const float* __restrict__ w3, const float* __restrict__ w4,
                          __half* __restrict__ w1c, __half* __restrict__ w2c,
                          __half* __restrict__ w3c, __half* __restrict__ w4c)
{
    int idx = blockIdx.x * blockDim.x + threadIdx.x;
    if (idx < WSEG1) {
        int n = idx / TP_, k = idx - n * TP_;
        w1c[idx] = (k < TN_) ? __float2half_rn(w1[n * TN_ + k]) : __float2half_rn(0.0f);
        return;
    }
    idx -= WSEG1;
    if (idx < WSEG2) { w2c[idx] = __float2half_rn(w2[idx]); return; }
    idx -= WSEG2;
    if (idx < WSEG3) { w3c[idx] = __float2half_rn(w3[idx]); return; }
    idx -= WSEG3;
    if (idx < WSEG4) {
        int n = idx / D3_, k = idx - n * D3_;
        w4c[idx] = (n < TN_) ? __float2half_rn(w4[n * D3_ + k]) : __float2half_rn(0.0f);
    }
}

// ---------------- input projection (known good) ----------------
__global__ __launch_bounds__(256)
void xw_kernel(const float* __restrict__ x,
               const float* __restrict__ Wih,
               const float* __restrict__ bih,
               const float* __restrict__ bhh,
               float* __restrict__ xwT)
{
    __shared__ float sm[32 * 33];
    int tid = threadIdx.x;
    int lane = tid & 31, w = tid >> 5;
    int b0 = blockIdx.x * 32;

    float w0 = Wih[0], w1 = Wih[1], w2 = Wih[2], w3 = Wih[3];
    float w4 = Wih[4], w5 = Wih[5], w6 = Wih[6];
    float bias = bih[0] + bhh[0];

    for (int t0 = 0; t0 < TN_; t0 += 32) {
        #pragma unroll
        for (int rr = 0; rr < 4; rr++) {
            int r = w + rr * 8;
            int t = t0 + lane;
            float v = 0.0f;
            if (t < TN_) {
                const float* p = x + ((size_t)(b0 + r) * TN_ + t) * IN_;
                v = bias;
                v = fmaf(p[0], w0, v);
                v = fmaf(p[1], w1, v);
                v = fmaf(p[2], w2, v);
                v = fmaf(p[3], w3, v);
                v = fmaf(p[4], w4, v);
                v = fmaf(p[5], w5, v);
                v = fmaf(p[6], w6, v);
            }
            sm[lane * 33 + r] = v;
        }
        __syncthreads();
        #pragma unroll
        for (int i = 0; i < 4; i++) {
            int tt = w * 4 + i;
            int t = t0 + tt;
            if (t < TN_) xwT[(size_t)t * BN_ + b0 + lane] = sm[tt * 33 + lane];
        }
        __syncthreads();
    }
}

// ---------------- RNN: recurrence with cp.async smem ring (known good) ----------------
#define RNN_TILES  (TP_ / 32)          // 21
#define RNN_STAGE  (32 * 128)          // floats per stage
#define RNN_SMEM   (4 * RNN_STAGE * 4) // 64 KB

__global__ __launch_bounds__(128)
void rnn_kernel(const float* __restrict__ xwT,
                const float* __restrict__ h0,
                const float* __restrict__ Whh,
                __half* __restrict__ hsT,
                float* __restrict__ hidden)
{
    extern __shared__ float ring[];
    int tid = threadIdx.x;
    int b0 = blockIdx.x * 128;
    int b = b0 + tid;

    float a = Whh[0];
    float h = h0[b];

    auto load_tile = [&](int tt) {
        int t0 = tt * 32;
        float* dst = ring + (tt & 3) * RNN_STAGE;
        #pragma unroll
        for (int i = 0; i < 8; i++) {
            int c = i * 128 + tid;
            int r = c >> 5, co = (c & 31) << 2;
            int t = t0 + r;
            if (t < TN_)
                CP16(smem_u32(dst + r * 128 + co), xwT + (size_t)t * BN_ + b0 + co);
        }
        CP_COMMIT();
    };

    load_tile(0); load_tile(1); load_tile(2);

    for (int tt = 0; tt < RNN_TILES; tt++) {
        if (tt + 3 < RNN_TILES) load_tile(tt + 3);
        else                    CP_COMMIT();
        CP_WAIT2();
        __syncthreads();

        int t0 = tt * 32;
        const float* col = ring + (tt & 3) * RNN_STAGE + tid;
        int jmax = (TN_ - t0 < 32) ? (TN_ - t0) : 32;
        float nxt = col[0];
        #pragma unroll 4
        for (int j = 0; j < jmax; j++) {
            float cur = nxt;
            if (j + 1 < jmax) nxt = col[(j + 1) * 128];
            h = tanhf(fmaf(a, h, cur));
            hsT[(size_t)(t0 + j) * BN_ + b] = __float2half_rn(h);
        }
        __syncthreads();
    }

    #pragma unroll
    for (int t = TN_; t < TP_; t++) hsT[(size_t)t * BN_ + b] = __float2half_rn(0.0f);
    if (hidden) hidden[b] = h;
}

// ---------------- fp16 mma GEMM (m16n8k16, fp32 accum, 3-stage) ----------------
// C[m,n] = sum_k A[m,k]*B[n,k] + bias[n]. BM = MT*32, BN = 128, BK = 32 halves.
// 256 threads = 8 warps (2 m x 4 n), warp tile (MT*16) x 32.
// ATRANS: A is AT[k][M] halves; smem A [32][136] halves, fragments via ldmatrix.trans.
// else:   A row-major [M][K] halves; smem A [BM][40] halves, plain ldmatrix.
template<int MT, bool ATRANS, bool RELU, bool GUARDN, bool OUTF32>
__global__ __launch_bounds__(256, 2)
void gemm_h(const __half* __restrict__ A, int lda,
            const __half* __restrict__ Bw, int ldb,
            const float* __restrict__ bias,
            void* __restrict__ Cv, int ldc, int Nreal, int K)
{
    constexpr int BM = MT * 32;
    constexpr int A_STAGE = ATRANS ? 32 * 136 : BM * 40;   // halves
    constexpr int B_STAGE = 128 * 40;

    extern __shared__ __half smh[];
    __half* As = smh;
    __half* Bs = smh + 3 * A_STAGE;

    int tid = threadIdx.x;
    int lane = tid & 31;
    int wid  = tid >> 5;
    int wm = wid & 1;
    int wn = wid >> 1;
    int grp = lane >> 2;
    int qk  = lane & 3;
    int m0 = blockIdx.y * BM;
    int n0 = blockIdx.x * 128;

    // ldmatrix per-lane base addresses (bytes)
    uint32_t aBase;
    if (ATRANS) {
        int kRow = (lane & 7) + ((lane >> 4) & 1) * 8;
        int mCol = wm * (MT * 16) + ((lane >> 3) & 1) * 8;
        aBase = smem_u32(As) + (uint32_t)(kRow * 136 + mCol) * 2;
    } else {
        int aRow = wm * (MT * 16) + (lane & 7) + ((lane >> 3) & 1) * 8;
        int aCol = ((lane >> 4) & 1) * 8;
        aBase = smem_u32(As) + (uint32_t)(aRow * 40 + aCol) * 2;
    }
    int bRow = wn * 32 + (lane & 7) + ((lane >> 4) & 1) * 8;
    int bCol = ((lane >> 3) & 1) * 8;
    uint32_t bBase = smem_u32(Bs) + (uint32_t)(bRow * 40 + bCol) * 2;

    float acc[MT][4][4];
    #pragma unroll
    for (int i = 0; i < MT; i++)
        #pragma unroll
        for (int j = 0; j < 4; j++)
            #pragma unroll
            for (int q = 0; q < 4; q++) acc[i][j][q] = 0.0f;

    const int KT = K >> 5;

    auto load_stage = [&](int kt, int s) {
        __half* aS = As + s * A_STAGE;
        __half* bS = Bs + s * B_STAGE;
        if (ATRANS) {
            const __half* Ap = A + (size_t)(kt * 32) * lda + m0;
            #pragma unroll
            for (int i = 0; i < 2; i++) {          // 32 k-rows x 16 chunks of 16B
                int c = i * 256 + tid;
                int r = c >> 4, co = (c & 15) << 3;
                CP16(smem_u32(aS + r * 136 + co), Ap + (size_t)r * lda + co);
            }
        } else {
            const __half* Ap = A + (size_t)m0 * lda + kt * 32;
            #pragma unroll
            for (int i = 0; i < BM / 64; i++) {    // BM rows x 4 chunks of 16B
                int c = i * 256 + tid;
                int r = c >> 2, co = (c & 3) << 3;
                CP16(smem_u32(aS + r * 40 + co), Ap + (size_t)r * lda + co);
            }
        }
        const __half* Bp = Bw + (size_t)n0 * ldb + kt * 32;
        #pragma unroll
        for (int i = 0; i < 2; i++) {
            int c = i * 256 + tid;
            int r = c >> 2, co = (c & 3) << 3;
            CP16(smem_u32(bS + r * 40 + co), Bp + (size_t)r * ldb + co);
        }
        CP_COMMIT();
    };

    load_stage(0, 0);
    if (KT > 1) load_stage(1, 1); else CP_COMMIT();

    for (int kt = 0; kt < KT; kt++) {
        int s = kt % 3;
        if (kt + 2 < KT) load_stage(kt + 2, (kt + 2) % 3);
        else             CP_COMMIT();
        CP_WAIT2();
        __syncthreads();

        uint32_t aSt = aBase + (uint32_t)(s * A_STAGE) * 2;
        uint32_t bSt = bBase + (uint32_t)(s * B_STAGE) * 2;

        #pragma unroll
        for (int ks = 0; ks < 2; ks++) {           // 2 x k16
            uint32_t af[MT][4], bf[4][2];
            if (ATRANS) {
                uint32_t aAddr = aSt + (uint32_t)(ks * 16 * 136) * 2;
                #pragma unroll
                for (int mt = 0; mt < MT; mt++)
                    LDSM4T(af[mt][0], af[mt][1], af[mt][2], af[mt][3],
                           aAddr + (uint32_t)(mt * 16) * 2);
            } else {
                uint32_t aAddr = aSt + ks * 32;
                #pragma unroll
                for (int mt = 0; mt < MT; mt++)
                    LDSM4(af[mt][0], af[mt][1], af[mt][2], af[mt][3],
                          aAddr + (uint32_t)(mt * 16 * 40) * 2);
            }
            uint32_t bAddr = bSt + ks * 32;
            #pragma unroll
            for (int ntp = 0; ntp < 2; ntp++)
                LDSM4(bf[2 * ntp][0], bf[2 * ntp][1], bf[2 * ntp + 1][0], bf[2 * ntp + 1][1],
                      bAddr + (uint32_t)(ntp * 16 * 40) * 2);
            #pragma unroll
            for (int mt = 0; mt < MT; mt++)
                #pragma unroll
                for (int nt = 0; nt < 4; nt++)
                    mma_f16(acc[mt][nt], af[mt], bf[nt]);
        }
        __syncthreads();
    }

    // ---- epilogue ----
    #pragma unroll
    for (int mt = 0; mt < MT; mt++) {
        int r0 = m0 + wm * (MT * 16) + mt * 16 + grp;
        #pragma unroll
        for (int nt = 0; nt < 4; nt++) {
            int nc = n0 + wn * 32 + nt * 8 + 2 * qk;
            if (GUARDN && nc >= Nreal) continue;
            float b0v = bias[nc], b1v = bias[nc + 1];
            float v00 = acc[mt][nt][0] + b0v, v01 = acc[mt][nt][1] + b1v;
            float v10 = acc[mt][nt][2] + b0v, v11 = acc[mt][nt][3] + b1v;
            if (RELU) {
                v00 = fmaxf(v00, 0.0f); v01 = fmaxf(v01, 0.0f);
                v10 = fmaxf(v10, 0.0f); v11 = fmaxf(v11, 0.0f);
            }
            if (OUTF32) {
                float* C = (float*)Cv;
                *(float2*)(C + (size_t)r0 * ldc + nc)       = make_float2(v00, v01);
                *(float2*)(C + (size_t)(r0 + 8) * ldc + nc) = make_float2(v10, v11);
            } else {
                __half* C = (__half*)Cv;
                *(__half2*)(C + (size_t)r0 * ldc + nc)       = __floats2half2_rn(v00, v01);
                *(__half2*)(C + (size_t)(r0 + 8) * ldc + nc) = __floats2half2_rn(v10, v11);
            }
        }
    }
}

// ---------------- launcher ----------------
#define SMEM_G1  (3 * (32 * 136 + 128 * 40) * 2)
#define SMEM_MT4 (3 * (128 * 40 + 128 * 40) * 2)
#define SMEM_MT2 (3 * (64 * 40 + 128 * 40) * 2)

extern "C" void kernel_launch(void* const* d_in, const int* in_sizes, int n_in,
                              void* d_out, int out_size)
{
    const float* x   = (const float*)d_in[0];
    const float* h0  = (const float*)d_in[1];
    const float* Wih = (const float*)d_in[2];
    const float* Whh = (const float*)d_in[3];
    const float* bih = (const float*)d_in[4];
    const float* bhh = (const float*)d_in[5];
    const float* w1  = (const float*)d_in[6];
    const float* b1  = (const float*)d_in[7];
    const float* w2  = (const float*)d_in[8];
    const float* b2  = (const float*)d_in[9];
    const float* w3  = (const float*)d_in[10];
    const float* b3  = (const float*)d_in[11];
    const float* w4  = (const float*)d_in[12];
    const float* b4  = (const float*)d_in[13];
    float* out = (float*)d_out;

    float *xwT;
    __half *hsT, *c1, *c2, *c3, *w1c, *w2c, *w3c, *w4c;
    cudaGetSymbolAddress((void**)&xwT, g_xwT);
    cudaGetSymbolAddress((void**)&hsT, g_hsT);
    cudaGetSymbolAddress((void**)&c1,  g_c1);
    cudaGetSymbolAddress((void**)&c2,  g_c2);
    cudaGetSymbolAddress((void**)&c3,  g_c3);
    cudaGetSymbolAddress((void**)&w1c, g_w1c);
    cudaGetSymbolAddress((void**)&w2c, g_w2c);
    cudaGetSymbolAddress((void**)&w3c, g_w3c);
    cudaGetSymbolAddress((void**)&w4c, g_w4c);

    cudaFuncSetAttribute(rnn_kernel, cudaFuncAttributeMaxDynamicSharedMemorySize, RNN_SMEM);
    cudaFuncSetAttribute(gemm_h<4, true,  true,  false, false>, cudaFuncAttributeMaxDynamicSharedMemorySize, SMEM_G1);
    cudaFuncSetAttribute(gemm_h<4, false, true,  false, false>, cudaFuncAttributeMaxDynamicSharedMemorySize, SMEM_MT4);
    cudaFuncSetAttribute(gemm_h<2, false, true,  false, false>, cudaFuncAttributeMaxDynamicSharedMemorySize, SMEM_MT2);
    cudaFuncSetAttribute(gemm_h<4, false, false, true,  true >, cudaFuncAttributeMaxDynamicSharedMemorySize, SMEM_MT4);

    // weight prep (single fused launch, fp32 -> fp16 + pad)
    wprep_all<<<(WTOT + 255) / 256, 256>>>(w1, w2, w3, w4, w1c, w2c, w3c, w4c);

    // input projection, then recurrence with deep prefetch (hsT fp16 [t][b])
    xw_kernel<<<BN_ / 32, 256>>>(x, Wih, bih, bhh, xwT);
    float* hidden = (out_size >= BN_ * TN_ + BN_) ? (out + (size_t)BN_ * TN_) : nullptr;
    rnn_kernel<<<BN_ / 128, 128, RNN_SMEM>>>(xwT, h0, Whh, hsT, hidden);

    // GEMM chain on fp16 mma (fp32 accumulate)
    gemm_h<4, true,  true,  false, false><<<dim3(D1_ / 128, BN_ / 128), 256, SMEM_G1 >>>(hsT, BN_, w1c, TP_,  b1, c1,  D1_, D1_, TP_);
    gemm_h<4, false, true,  false, false><<<dim3(D2_ / 128, BN_ / 128), 256, SMEM_MT4>>>(c1,  D1_, w2c, D1_,  b2, c2,  D2_, D2_, D1_);
    gemm_h<2, false, true,  false, false><<<dim3(D3_ / 128, BN_ / 64 ), 256, SMEM_MT2>>>(c2,  D2_, w3c, D2_,  b3, c3,  D3_, D3_, D2_);
    gemm_h<4, false, false, true,  true ><<<dim3(N4P_ / 128, BN_ / 128), 256, SMEM_MT4>>>(c3,  D3_, w4c, D3_,  b4, out, TN_, TN_, D3_);
}

// round 11
// speedup vs baseline: 2.9543x; 1.1904x over previous
#include <cuda_runtime.h>
#include <cuda_fp16.h>
#include <math.h>
#include <stdint.h>

// ---------------- problem constants ----------------
#define BN_  8192   // batch (GEMM M)
#define TN_  658    // seq len / final out features
#define TP_  672    // K-pad for layer1 (21 * 32)
#define IN_  7
#define D1_  1024
#define D2_  512
#define D3_  128
#define N4P_ 768    // w4 N padded (658 -> 768)

// ---------------- scratch ----------------
__device__ float  g_xwT[(size_t)TN_ * BN_];   // [t][b] input projection (fp32)
__device__ __half g_hsT[(size_t)TP_ * BN_];   // [t][b] fp16, K-padded (A^T of GEMM1)
__device__ __half g_c1 [(size_t)BN_ * D1_];
__device__ __half g_c2 [(size_t)BN_ * D2_];
__device__ __half g_c3 [(size_t)BN_ * D3_];
__device__ __half g_w1c[D1_ * TP_];
__device__ __half g_w2c[D2_ * D1_];
__device__ __half g_w3c[D3_ * D2_];
__device__ __half g_w4c[N4P_ * D3_];

// ---------------- helpers ----------------
__device__ __forceinline__ uint32_t smem_u32(const void* p) {
    uint32_t a;
    asm("{ .reg .u64 t; cvta.to.shared.u64 t, %1; cvt.u32.u64 %0, t; }" : "=r"(a) : "l"(p));
    return a;
}
#define CP16(sa, ga) asm volatile("cp.async.cg.shared.global [%0], [%1], 16;" :: "r"(sa), "l"(ga))
#define CP8(sa, ga)  asm volatile("cp.async.ca.shared.global [%0], [%1], 8;"  :: "r"(sa), "l"(ga))
#define CP_COMMIT()  asm volatile("cp.async.commit_group;" ::: "memory")
#define CP_WAIT0()   asm volatile("cp.async.wait_group 0;" ::: "memory")
#define CP_WAIT1()   asm volatile("cp.async.wait_group 1;" ::: "memory")
#define CP_WAIT2()   asm volatile("cp.async.wait_group 2;" ::: "memory")

#define LDSM4(r0, r1, r2, r3, a)                                                 \
    asm volatile("ldmatrix.sync.aligned.m8n8.x4.shared.b16 {%0,%1,%2,%3}, [%4];" \
        : "=r"(r0), "=r"(r1), "=r"(r2), "=r"(r3) : "r"(a))
#define LDSM4T(r0, r1, r2, r3, a)                                                      \
    asm volatile("ldmatrix.sync.aligned.m8n8.x4.trans.shared.b16 {%0,%1,%2,%3}, [%4];" \
        : "=r"(r0), "=r"(r1), "=r"(r2), "=r"(r3) : "r"(a))

__device__ __forceinline__ void mma_f16(float* d, const uint32_t* a, const uint32_t* b) {
    asm volatile(
        "mma.sync.aligned.m16n8k16.row.col.f32.f16.f16.f32 "
        "{%0,%1,%2,%3}, {%4,%5,%6,%7}, {%8,%9}, {%0,%1,%2,%3};"
        : "+f"(d[0]), "+f"(d[1]), "+f"(d[2]), "+f"(d[3])
        : "r"(a[0]), "r"(a[1]), "r"(a[2]), "r"(a[3]), "r"(b[0]), "r"(b[1]));
}

// ---------------- fused weight prep (pad + fp16 convert) ----------------
#define WSEG1 (D1_ * TP_)
#define WSEG2 (D2_ * D1_)
#define WSEG3 (D3_ * D2_)
#define WSEG4 (N4P_ * D3_)
#define WTOT  (WSEG1 + WSEG2 + WSEG3 + WSEG4)

__global__ void wprep_all(const float* __restrict__ w1, const float* __restrict__ w2,
                          const float* __restrict__ w3, const float* __restrict__ w4,
                          __half* __restrict__ w1c, __half* __restrict__ w2c,
                          __half* __restrict__ w3c, __half* __restrict__ w4c)
{
    int idx = blockIdx.x * blockDim.x + threadIdx.x;
    if (idx < WSEG1) {
        int n = idx / TP_, k = idx - n * TP_;
        w1c[idx] = (k < TN_) ? __float2half_rn(w1[n * TN_ + k]) : __float2half_rn(0.0f);
        return;
    }
    idx -= WSEG1;
    if (idx < WSEG2) { w2c[idx] = __float2half_rn(w2[idx]); return; }
    idx -= WSEG2;
    if (idx < WSEG3) { w3c[idx] = __float2half_rn(w3[idx]); return; }
    idx -= WSEG3;
    if (idx < WSEG4) {
        int n = idx / D3_, k = idx - n * D3_;
        w4c[idx] = (n < TN_) ? __float2half_rn(w4[n * D3_ + k]) : __float2half_rn(0.0f);
    }
}

// ---------------- input projection v3: coalesced staging ----------------
// Block = 256 threads, 32 b's. t-tiles of 32, double-buffered cp.async (float2).
// Stage: 32 rows x 226 floats (226 even -> 8B alignment preserved; 2-way bank
// conflict max on compute reads). Compute: thread (b=lane, tgroup=warp) -> 4 t's;
// stores xwT[t][b0+lane] coalesced.
#define XW_TT     32
#define XW_NT     ((TN_ + XW_TT - 1) / XW_TT)      // 21
#define XW_STRIDE 226
#define XW_STAGE  (32 * XW_STRIDE)                 // floats
#define XW_SMEM   (2 * XW_STAGE * 4)               // 57856 B

__global__ __launch_bounds__(256)
void xw_kernel(const float* __restrict__ x,
               const float* __restrict__ Wih,
               const float* __restrict__ bih,
               const float* __restrict__ bhh,
               float* __restrict__ xwT)
{
    extern __shared__ float raw[];
    int tid = threadIdx.x;
    int lane = tid & 31, grp = tid >> 5;
    int b0 = blockIdx.x * 32;

    float w0 = Wih[0], w1 = Wih[1], w2 = Wih[2], w3 = Wih[3];
    float w4 = Wih[4], w5 = Wih[5], w6 = Wih[6];
    float bias = bih[0] + bhh[0];

    auto load_tile = [&](int tt) {
        int t0 = tt * XW_TT;
        int nt = (TN_ - t0 < XW_TT) ? (TN_ - t0) : XW_TT;
        int nf2 = nt * IN_ / 2;                    // 112 or 63 (always integral)
        float* dst = raw + (tt & 1) * XW_STAGE;
        int tot = 32 * nf2;
        for (int c = tid; c < tot; c += 256) {
            int r = c / nf2, o = c - r * nf2;
            CP8(smem_u32(dst + r * XW_STRIDE + 2 * o),
                x + (size_t)(b0 + r) * (TN_ * IN_) + t0 * IN_ + 2 * o);
        }
        CP_COMMIT();
    };

    load_tile(0);

    for (int tt = 0; tt < XW_NT; tt++) {
        if (tt + 1 < XW_NT) load_tile(tt + 1);
        else                CP_COMMIT();
        CP_WAIT1();
        __syncthreads();

        const float* src = raw + (tt & 1) * XW_STAGE + lane * XW_STRIDE;
        int t0 = tt * XW_TT;
        #pragma unroll
        for (int i = 0; i < 4; i++) {
            int tl = grp * 4 + i;
            int t = t0 + tl;
            if (t < TN_) {
                const float* p = src + tl * IN_;
                float v = bias;
                v = fmaf(p[0], w0, v);
                v = fmaf(p[1], w1, v);
                v = fmaf(p[2], w2, v);
                v = fmaf(p[3], w3, v);
                v = fmaf(p[4], w4, v);
                v = fmaf(p[5], w5, v);
                v = fmaf(p[6], w6, v);
                xwT[(size_t)t * BN_ + b0 + lane] = v;
            }
        }
        __syncthreads();
    }
}

// ---------------- RNN: recurrence with cp.async smem ring (known good) ----------------
#define RNN_TILES  (TP_ / 32)          // 21
#define RNN_STAGE  (32 * 128)          // floats per stage
#define RNN_SMEM   (4 * RNN_STAGE * 4) // 64 KB

__global__ __launch_bounds__(128)
void rnn_kernel(const float* __restrict__ xwT,
                const float* __restrict__ h0,
                const float* __restrict__ Whh,
                __half* __restrict__ hsT,
                float* __restrict__ hidden)
{
    extern __shared__ float ring[];
    int tid = threadIdx.x;
    int b0 = blockIdx.x * 128;
    int b = b0 + tid;

    float a = Whh[0];
    float h = h0[b];

    auto load_tile = [&](int tt) {
        int t0 = tt * 32;
        float* dst = ring + (tt & 3) * RNN_STAGE;
        #pragma unroll
        for (int i = 0; i < 8; i++) {
            int c = i * 128 + tid;
            int r = c >> 5, co = (c & 31) << 2;
            int t = t0 + r;
            if (t < TN_)
                CP16(smem_u32(dst + r * 128 + co), xwT + (size_t)t * BN_ + b0 + co);
        }
        CP_COMMIT();
    };

    load_tile(0); load_tile(1); load_tile(2);

    for (int tt = 0; tt < RNN_TILES; tt++) {
        if (tt + 3 < RNN_TILES) load_tile(tt + 3);
        else                    CP_COMMIT();
        CP_WAIT2();
        __syncthreads();

        int t0 = tt * 32;
        const float* col = ring + (tt & 3) * RNN_STAGE + tid;
        int jmax = (TN_ - t0 < 32) ? (TN_ - t0) : 32;
        float nxt = col[0];
        #pragma unroll 4
        for (int j = 0; j < jmax; j++) {
            float cur = nxt;
            if (j + 1 < jmax) nxt = col[(j + 1) * 128];
            h = tanhf(fmaf(a, h, cur));
            hsT[(size_t)(t0 + j) * BN_ + b] = __float2half_rn(h);
        }
        __syncthreads();
    }

    #pragma unroll
    for (int t = TN_; t < TP_; t++) hsT[(size_t)t * BN_ + b] = __float2half_rn(0.0f);
    if (hidden) hidden[b] = h;
}

// ---------------- fp16 mma GEMM (m16n8k16, fp32 accum, 3-stage) ----------------
template<int MT, bool ATRANS, bool RELU, bool GUARDN, bool OUTF32>
__global__ __launch_bounds__(256, 2)
void gemm_h(const __half* __restrict__ A, int lda,
            const __half* __restrict__ Bw, int ldb,
            const float* __restrict__ bias,
            void* __restrict__ Cv, int ldc, int Nreal, int K)
{
    constexpr int BM = MT * 32;
    constexpr int A_STAGE = ATRANS ? 32 * 136 : BM * 40;   // halves
    constexpr int B_STAGE = 128 * 40;

    extern __shared__ __half smh[];
    __half* As = smh;
    __half* Bs = smh + 3 * A_STAGE;

    int tid = threadIdx.x;
    int lane = tid & 31;
    int wid  = tid >> 5;
    int wm = wid & 1;
    int wn = wid >> 1;
    int grp = lane >> 2;
    int qk  = lane & 3;
    int m0 = blockIdx.y * BM;
    int n0 = blockIdx.x * 128;

    uint32_t aBase;
    if (ATRANS) {
        int kRow = (lane & 7) + ((lane >> 4) & 1) * 8;
        int mCol = wm * (MT * 16) + ((lane >> 3) & 1) * 8;
        aBase = smem_u32(As) + (uint32_t)(kRow * 136 + mCol) * 2;
    } else {
        int aRow = wm * (MT * 16) + (lane & 7) + ((lane >> 3) & 1) * 8;
        int aCol = ((lane >> 4) & 1) * 8;
        aBase = smem_u32(As) + (uint32_t)(aRow * 40 + aCol) * 2;
    }
    int bRow = wn * 32 + (lane & 7) + ((lane >> 4) & 1) * 8;
    int bCol = ((lane >> 3) & 1) * 8;
    uint32_t bBase = smem_u32(Bs) + (uint32_t)(bRow * 40 + bCol) * 2;

    float acc[MT][4][4];
    #pragma unroll
    for (int i = 0; i < MT; i++)
        #pragma unroll
        for (int j = 0; j < 4; j++)
            #pragma unroll
            for (int q = 0; q < 4; q++) acc[i][j][q] = 0.0f;

    const int KT = K >> 5;

    auto load_stage = [&](int kt, int s) {
        __half* aS = As + s * A_STAGE;
        __half* bS = Bs + s * B_STAGE;
        if (ATRANS) {
            const __half* Ap = A + (size_t)(kt * 32) * lda + m0;
            #pragma unroll
            for (int i = 0; i < 2; i++) {
                int c = i * 256 + tid;
                int r = c >> 4, co = (c & 15) << 3;
                CP16(smem_u32(aS + r * 136 + co), Ap + (size_t)r * lda + co);
            }
        } else {
            const __half* Ap = A + (size_t)m0 * lda + kt * 32;
            #pragma unroll
            for (int i = 0; i < BM / 64; i++) {
                int c = i * 256 + tid;
                int r = c >> 2, co = (c & 3) << 3;
                CP16(smem_u32(aS + r * 40 + co), Ap + (size_t)r * lda + co);
            }
        }
        const __half* Bp = Bw + (size_t)n0 * ldb + kt * 32;
        #pragma unroll
        for (int i = 0; i < 2; i++) {
            int c = i * 256 + tid;
            int r = c >> 2, co = (c & 3) << 3;
            CP16(smem_u32(bS + r * 40 + co), Bp + (size_t)r * ldb + co);
        }
        CP_COMMIT();
    };

    load_stage(0, 0);
    if (KT > 1) load_stage(1, 1); else CP_COMMIT();

    for (int kt = 0; kt < KT; kt++) {
        int s = kt % 3;
        if (kt + 2 < KT) load_stage(kt + 2, (kt + 2) % 3);
        else             CP_COMMIT();
        CP_WAIT2();
        __syncthreads();

        uint32_t aSt = aBase + (uint32_t)(s * A_STAGE) * 2;
        uint32_t bSt = bBase + (uint32_t)(s * B_STAGE) * 2;

        #pragma unroll
        for (int ks = 0; ks < 2; ks++) {
            uint32_t af[MT][4], bf[4][2];
            if (ATRANS) {
                uint32_t aAddr = aSt + (uint32_t)(ks * 16 * 136) * 2;
                #pragma unroll
                for (int mt = 0; mt < MT; mt++)
                    LDSM4T(af[mt][0], af[mt][1], af[mt][2], af[mt][3],
                           aAddr + (uint32_t)(mt * 16) * 2);
            } else {
                uint32_t aAddr = aSt + ks * 32;
                #pragma unroll
                for (int mt = 0; mt < MT; mt++)
                    LDSM4(af[mt][0], af[mt][1], af[mt][2], af[mt][3],
                          aAddr + (uint32_t)(mt * 16 * 40) * 2);
            }
            uint32_t bAddr = bSt + ks * 32;
            #pragma unroll
            for (int ntp = 0; ntp < 2; ntp++)
                LDSM4(bf[2 * ntp][0], bf[2 * ntp][1], bf[2 * ntp + 1][0], bf[2 * ntp + 1][1],
                      bAddr + (uint32_t)(ntp * 16 * 40) * 2);
            #pragma unroll
            for (int mt = 0; mt < MT; mt++)
                #pragma unroll
                for (int nt = 0; nt < 4; nt++)
                    mma_f16(acc[mt][nt], af[mt], bf[nt]);
        }
        __syncthreads();
    }

    // ---- epilogue ----
    #pragma unroll
    for (int mt = 0; mt < MT; mt++) {
        int r0 = m0 + wm * (MT * 16) + mt * 16 + grp;
        #pragma unroll
        for (int nt = 0; nt < 4; nt++) {
            int nc = n0 + wn * 32 + nt * 8 + 2 * qk;
            if (GUARDN && nc >= Nreal) continue;
            float b0v = bias[nc], b1v = bias[nc + 1];
            float v00 = acc[mt][nt][0] + b0v, v01 = acc[mt][nt][1] + b1v;
            float v10 = acc[mt][nt][2] + b0v, v11 = acc[mt][nt][3] + b1v;
            if (RELU) {
                v00 = fmaxf(v00, 0.0f); v01 = fmaxf(v01, 0.0f);
                v10 = fmaxf(v10, 0.0f); v11 = fmaxf(v11, 0.0f);
            }
            if (OUTF32) {
                float* C = (float*)Cv;
                *(float2*)(C + (size_t)r0 * ldc + nc)       = make_float2(v00, v01);
                *(float2*)(C + (size_t)(r0 + 8) * ldc + nc) = make_float2(v10, v11);
            } else {
                __half* C = (__half*)Cv;
                *(__half2*)(C + (size_t)r0 * ldc + nc)       = __floats2half2_rn(v00, v01);
                *(__half2*)(C + (size_t)(r0 + 8) * ldc + nc) = __floats2half2_rn(v10, v11);
            }
        }
    }
}

// ---------------- launcher ----------------
#define SMEM_G1  (3 * (32 * 136 + 128 * 40) * 2)
#define SMEM_MT4 (3 * (128 * 40 + 128 * 40) * 2)
#define SMEM_MT2 (3 * (64 * 40 + 128 * 40) * 2)

extern "C" void kernel_launch(void* const* d_in, const int* in_sizes, int n_in,
                              void* d_out, int out_size)
{
    const float* x   = (const float*)d_in[0];
    const float* h0  = (const float*)d_in[1];
    const float* Wih = (const float*)d_in[2];
    const float* Whh = (const float*)d_in[3];
    const float* bih = (const float*)d_in[4];
    const float* bhh = (const float*)d_in[5];
    const float* w1  = (const float*)d_in[6];
    const float* b1  = (const float*)d_in[7];
    const float* w2  = (const float*)d_in[8];
    const float* b2  = (const float*)d_in[9];
    const float* w3  = (const float*)d_in[10];
    const float* b3  = (const float*)d_in[11];
    const float* w4  = (const float*)d_in[12];
    const float* b4  = (const float*)d_in[13];
    float* out = (float*)d_out;

    float *xwT;
    __half *hsT, *c1, *c2, *c3, *w1c, *w2c, *w3c, *w4c;
    cudaGetSymbolAddress((void**)&xwT, g_xwT);
    cudaGetSymbolAddress((void**)&hsT, g_hsT);
    cudaGetSymbolAddress((void**)&c1,  g_c1);
    cudaGetSymbolAddress((void**)&c2,  g_c2);
    cudaGetSymbolAddress((void**)&c3,  g_c3);
    cudaGetSymbolAddress((void**)&w1c, g_w1c);
    cudaGetSymbolAddress((void**)&w2c, g_w2c);
    cudaGetSymbolAddress((void**)&w3c, g_w3c);
    cudaGetSymbolAddress((void**)&w4c, g_w4c);

    cudaFuncSetAttribute(xw_kernel,  cudaFuncAttributeMaxDynamicSharedMemorySize, XW_SMEM);
    cudaFuncSetAttribute(rnn_kernel, cudaFuncAttributeMaxDynamicSharedMemorySize, RNN_SMEM);
    cudaFuncSetAttribute(gemm_h<4, true,  true,  false, false>, cudaFuncAttributeMaxDynamicSharedMemorySize, SMEM_G1);
    cudaFuncSetAttribute(gemm_h<4, false, true,  false, false>, cudaFuncAttributeMaxDynamicSharedMemorySize, SMEM_MT4);
    cudaFuncSetAttribute(gemm_h<2, false, true,  false, false>, cudaFuncAttributeMaxDynamicSharedMemorySize, SMEM_MT2);
    cudaFuncSetAttribute(gemm_h<4, false, false, true,  true >, cudaFuncAttributeMaxDynamicSharedMemorySize, SMEM_MT4);

    // weight prep (single fused launch, fp32 -> fp16 + pad)
    wprep_all<<<(WTOT + 255) / 256, 256>>>(w1, w2, w3, w4, w1c, w2c, w3c, w4c);

    // input projection (coalesced staging), then recurrence with deep prefetch
    xw_kernel<<<BN_ / 32, 256, XW_SMEM>>>(x, Wih, bih, bhh, xwT);
    float* hidden = (out_size >= BN_ * TN_ + BN_) ? (out + (size_t)BN_ * TN_) : nullptr;
    rnn_kernel<<<BN_ / 128, 128, RNN_SMEM>>>(xwT, h0, Whh, hsT, hidden);

    // GEMM chain on fp16 mma (fp32 accumulate)
    gemm_h<4, true,  true,  false, false><<<dim3(D1_ / 128, BN_ / 128), 256, SMEM_G1 >>>(hsT, BN_, w1c, TP_,  b1, c1,  D1_, D1_, TP_);
    gemm_h<4, false, true,  false, false><<<dim3(D2_ / 128, BN_ / 128), 256, SMEM_MT4>>>(c1,  D1_, w2c, D1_,  b2, c2,  D2_, D2_, D1_);
    gemm_h<2, false, true,  false, false><<<dim3(D3_ / 128, BN_ / 64 ), 256, SMEM_MT2>>>(c2,  D2_, w3c, D2_,  b3, c3,  D3_, D3_, D2_);
    gemm_h<4, false, false, true,  true ><<<dim3(N4P_ / 128, BN_ / 128), 256, SMEM_MT4>>>(c3,  D3_, w4c, D3_,  b4, out, TN_, TN_, D3_);
}